// round 1
// baseline (speedup 1.0000x reference)
#include <cuda_runtime.h>
#include <cuda_bf16.h>
#include <math.h>

#define B_  16
#define C_  256
#define H_  128
#define W_  128
#define K_  12
#define HW_ (H_ * W_)

#define TW 16
#define TH 8
#define HALO_W 18
#define HALO_H 10
#define HALO_N (HALO_W * HALO_H)   // 180
#define HALO_PAD 192                // padded per-buffer stride (floats)

// ---------------- device scratch (allocation-free rule: __device__ globals) ---
__device__ float g_y[B_ * C_];        // GAP means
__device__ float g_gate[B_ * C_];     // ECA sigmoid gate
__device__ float g_aggw[B_ * C_ * 9]; // per-sample aggregated depthwise kernels

__device__ __forceinline__ float gelu_exact(float v) {
    return 0.5f * v * (1.0f + erff(v * 0.70710678118654752f));
}
__device__ __forceinline__ float sigmoidf_(float v) {
    return 1.0f / (1.0f + __expf(-v));
}

// ---------------- K1: global average pool per (b,c) ---------------------------
__global__ void gap_kernel(const float* __restrict__ x) {
    __shared__ float red[8];
    const int bc = blockIdx.x;
    const float4* xp = reinterpret_cast<const float4*>(x + (size_t)bc * HW_);
    float s = 0.f;
#pragma unroll
    for (int i = 0; i < 16; i++) {
        float4 v = xp[threadIdx.x + 256 * i];
        s += (v.x + v.y) + (v.z + v.w);
    }
#pragma unroll
    for (int o = 16; o; o >>= 1) s += __shfl_xor_sync(0xffffffffu, s, o);
    if ((threadIdx.x & 31) == 0) red[threadIdx.x >> 5] = s;
    __syncthreads();
    if (threadIdx.x < 8) {
        s = red[threadIdx.x];
#pragma unroll
        for (int o = 4; o; o >>= 1) s += __shfl_xor_sync(0x000000ffu, s, o);
        if (threadIdx.x == 0) g_y[bc] = s * (1.0f / (float)HW_);
    }
}

// ---------------- K2: ECA gate + attention MLP + softmax + kernel aggregation -
__global__ void attn_kernel(const float* __restrict__ w1, const float* __restrict__ b1,
                            const float* __restrict__ w2, const float* __restrict__ b2,
                            const float* __restrict__ kw, const float* __restrict__ eca) {
    const int b = blockIdx.x;
    const int t = threadIdx.x;              // 256 threads
    __shared__ float ysm[C_ + 2];
    __shared__ float psm[C_];
    __shared__ float hsm[C_];
    __shared__ float lsm[K_];
    __shared__ float alph[K_];

    ysm[t + 1] = g_y[b * C_ + t];
    if (t == 0) { ysm[0] = 0.f; ysm[C_ + 1] = 0.f; }
    __syncthreads();

    const float e0 = eca[0], e1 = eca[1], e2 = eca[2];
    float gate = sigmoidf_(e0 * ysm[t] + e1 * ysm[t + 1] + e2 * ysm[t + 2]);
    g_gate[b * C_ + t] = gate;
    psm[t] = gate * ysm[t + 1];
    __syncthreads();

    // hidden = gelu(p @ W1 + b1), W1 is (in=C, out=C) -> W1[c*C + t]
    float acc = b1[t];
    for (int c = 0; c < C_; c++) acc += psm[c] * w1[c * C_ + t];
    hsm[t] = gelu_exact(acc);
    __syncthreads();

    if (t < K_) {
        float l = b2[t];
        for (int c = 0; c < C_; c++) l += hsm[c] * w2[c * K_ + t];
        lsm[t] = l;
    }
    __syncthreads();

    if (t == 0) {
        float m = lsm[0];
#pragma unroll
        for (int k = 1; k < K_; k++) m = fmaxf(m, lsm[k]);
        float s = 0.f;
#pragma unroll
        for (int k = 0; k < K_; k++) { float e = __expf(lsm[k] - m); alph[k] = e; s += e; }
        float inv = 1.0f / s;
#pragma unroll
        for (int k = 0; k < K_; k++) alph[k] *= inv;
    }
    __syncthreads();

    // agg_w[b,c,3,3] = sum_k alpha_k * kernels_w[k,c,3,3]
    for (int idx = t; idx < C_ * 9; idx += 256) {
        float v = 0.f;
#pragma unroll
        for (int k = 0; k < K_; k++) v += alph[k] * kw[k * (C_ * 9) + idx];
        g_aggw[b * (C_ * 9) + idx] = v;
    }
}

// ---------------- K3: fused depthwise conv + LayerNorm(C) + GELU + residual ---
// one block = one 16x8 pixel tile, all 256 channels. 8 warps, each owns 32 channels.
#define SMEM_FLOATS (C_*TW*TH + C_*9 + C_ + C_ + C_ + 8*2*HALO_PAD + 2*8*(TW*TH) + 2*(TW*TH))
#define SMEM_BYTES  (SMEM_FLOATS * 4)

__global__ void __launch_bounds__(256, 1)
fused_kernel(const float* __restrict__ x, const float* __restrict__ gamma,
             const float* __restrict__ beta, float* __restrict__ out) {
    extern __shared__ float smem[];
    float* s_conv  = smem;                       // [256][128]
    float* s_w     = s_conv + C_ * TW * TH;      // [256*9] (gate NOT folded here)
    float* s_gate  = s_w + C_ * 9;               // [256]
    float* s_gamma = s_gate + C_;                // [256]
    float* s_beta  = s_gamma + C_;               // [256]
    float* s_halo  = s_beta + C_;                // [8 warps][2 bufs][192]
    float* s_part  = s_halo + 8 * 2 * HALO_PAD;  // [2][8][128]
    float* s_mu    = s_part + 2 * 8 * (TW * TH); // [128]
    float* s_rstd  = s_mu + (TW * TH);           // [128]

    const int tid  = threadIdx.x;
    const int warp = tid >> 5;
    const int lane = tid & 31;
    const int b    = blockIdx.z;
    const int h0   = blockIdx.y * TH;
    const int w0   = blockIdx.x * TW;

    // stage per-sample weights/gate/ln params
    for (int i = tid; i < C_ * 9; i += 256) s_w[i] = g_aggw[b * (C_ * 9) + i];
    s_gate[tid]  = g_gate[b * C_ + tid];
    s_gamma[tid] = gamma[tid];
    s_beta[tid]  = beta[tid];

    // per-lane halo addressing (fixed across channels)
    int  eoff[6];
    bool eval_[6];
#pragma unroll
    for (int i = 0; i < 6; i++) {
        int e  = lane + 32 * i;
        int r  = e / HALO_W;
        int cc = e - r * HALO_W;
        int gh = h0 - 1 + r;
        int gw = w0 - 1 + cc;
        bool v = (e < HALO_N) && (gh >= 0) && (gh < H_) && (gw >= 0) && (gw < W_);
        eval_[i] = v;
        eoff[i]  = v ? (gh * W_ + gw) : 0;
    }
    __syncthreads();

    const int c_begin = warp * 32;
    float psum[4] = {0.f, 0.f, 0.f, 0.f};
    float psq[4]  = {0.f, 0.f, 0.f, 0.f};
    float* halo0 = s_halo + warp * 2 * HALO_PAD;
    float* halo1 = halo0 + HALO_PAD;

    // prefetch first channel's halo
    {
        const float* xc = x + ((size_t)(b * C_ + c_begin)) * HW_;
#pragma unroll
        for (int i = 0; i < 6; i++) {
            float v = eval_[i] ? __ldg(xc + eoff[i]) : 0.f;
            halo0[lane + 32 * i] = v;   // max index 191 < HALO_PAD; OOB slots hold 0
        }
        __syncwarp();
    }

    float* cur = halo0;
    float* nxt = halo1;
    for (int ci = 0; ci < 32; ci++) {
        const int c = c_begin + ci;
        // prefetch next channel into registers (hides DRAM latency)
        float pre[6];
        if (ci < 31) {
            const float* xc = x + ((size_t)(b * C_ + c + 1)) * HW_;
#pragma unroll
            for (int i = 0; i < 6; i++) pre[i] = eval_[i] ? __ldg(xc + eoff[i]) : 0.f;
        }
        // gate-folded 3x3 weights
        const float g = s_gate[c];
        const float* wc = s_w + c * 9;
        const float w00 = wc[0]*g, w01 = wc[1]*g, w02 = wc[2]*g;
        const float w10 = wc[3]*g, w11 = wc[4]*g, w12 = wc[5]*g;
        const float w20 = wc[6]*g, w21 = wc[7]*g, w22 = wc[8]*g;
        float* cb = s_conv + c * (TW * TH);
#pragma unroll
        for (int q = 0; q < 4; q++) {
            const int p  = lane + 32 * q;
            const int ph = p >> 4;
            const int pw = p & 15;
            const float* hr = cur + ph * HALO_W + pw;
            float a;
            a  = w00 * hr[0]             + w01 * hr[1]             + w02 * hr[2];
            a += w10 * hr[HALO_W]        + w11 * hr[HALO_W + 1]    + w12 * hr[HALO_W + 2];
            a += w20 * hr[2 * HALO_W]    + w21 * hr[2 * HALO_W + 1]+ w22 * hr[2 * HALO_W + 2];
            cb[p]    = a;
            psum[q] += a;
            psq[q]  += a * a;
        }
        __syncwarp();
        if (ci < 31) {
#pragma unroll
            for (int i = 0; i < 6; i++) nxt[lane + 32 * i] = pre[i];
            __syncwarp();
            float* tswap = cur; cur = nxt; nxt = tswap;
        }
    }

    // cross-warp LayerNorm stats over C
#pragma unroll
    for (int q = 0; q < 4; q++) {
        const int p = lane + 32 * q;
        s_part[warp * (TW * TH) + p]                     = psum[q];
        s_part[8 * (TW * TH) + warp * (TW * TH) + p]     = psq[q];
    }
    __syncthreads();
    if (tid < TW * TH) {
        float s = 0.f, s2 = 0.f;
#pragma unroll
        for (int w = 0; w < 8; w++) {
            s  += s_part[w * (TW * TH) + tid];
            s2 += s_part[8 * (TW * TH) + w * (TW * TH) + tid];
        }
        const float mu  = s * (1.0f / (float)C_);
        const float var = s2 * (1.0f / (float)C_) - mu * mu;
        s_mu[tid]   = mu;
        s_rstd[tid] = rsqrtf(var + 1e-6f);
    }
    __syncthreads();

    // finalize: LN -> GELU -> + residual x, streamed out
    for (int ci = 0; ci < 32; ci++) {
        const int c = c_begin + ci;
        const float gm = s_gamma[c];
        const float bt = s_beta[c];
        const float* cb = s_conv + c * (TW * TH);
        const float* xc = x + ((size_t)(b * C_ + c)) * HW_;
        float* oc = out + ((size_t)(b * C_ + c)) * HW_;
#pragma unroll
        for (int q = 0; q < 4; q++) {
            const int p  = lane + 32 * q;
            const int ph = p >> 4;
            const int pw = p & 15;
            const int go = (h0 + ph) * W_ + (w0 + pw);
            const float v = (cb[p] - s_mu[p]) * s_rstd[p] * gm + bt;
            oc[go] = gelu_exact(v) + __ldg(xc + go);
        }
    }
}

// ---------------- launcher -----------------------------------------------------
extern "C" void kernel_launch(void* const* d_in, const int* in_sizes, int n_in,
                              void* d_out, int out_size) {
    const float* x     = (const float*)d_in[0];
    const float* w1    = (const float*)d_in[1];
    const float* b1    = (const float*)d_in[2];
    const float* w2    = (const float*)d_in[3];
    const float* b2    = (const float*)d_in[4];
    const float* kw    = (const float*)d_in[5];
    const float* eca   = (const float*)d_in[6];
    const float* gamma = (const float*)d_in[7];
    const float* beta  = (const float*)d_in[8];
    float* out = (float*)d_out;

    cudaFuncSetAttribute(fused_kernel, cudaFuncAttributeMaxDynamicSharedMemorySize,
                         SMEM_BYTES);

    gap_kernel<<<B_ * C_, 256>>>(x);
    attn_kernel<<<B_, 256>>>(w1, b1, w2, b2, kw, eca);
    dim3 grid(W_ / TW, H_ / TH, B_);
    fused_kernel<<<grid, 256, SMEM_BYTES>>>(x, gamma, beta, out);
}

// round 2
// speedup vs baseline: 1.4011x; 1.4011x over previous
#include <cuda_runtime.h>
#include <cuda_bf16.h>
#include <math.h>

#define B_  16
#define C_  256
#define H_  128
#define W_  128
#define K_  12
#define HW_ (H_ * W_)

#define TW 16
#define TH 8
#define NPIX (TW * TH)          // 128 pixels per tile
#define HALO_W 18
#define HALO_H 10
#define HALO_N (HALO_W * HALO_H)   // 180
#define HALO_PAD 192
#define NWARP 16                 // warps per block (512 threads)
#define NCH 16                   // channels per warp (256 / 16)
#define PFD 4                    // prefetch depth (channels ahead)

// ---------------- device scratch (allocation-free rule: __device__ globals) ---
__device__ float g_y[B_ * C_];
__device__ float g_gate[B_ * C_];
__device__ float g_aggw[B_ * C_ * 9];

__device__ __forceinline__ float gelu_exact(float v) {
    return 0.5f * v * (1.0f + erff(v * 0.70710678118654752f));
}
__device__ __forceinline__ float sigmoidf_(float v) {
    return 1.0f / (1.0f + __expf(-v));
}

// ---------------- K1: global average pool per (b,c) ---------------------------
__global__ void gap_kernel(const float* __restrict__ x) {
    __shared__ float red[8];
    const int bc = blockIdx.x;
    const float4* xp = reinterpret_cast<const float4*>(x + (size_t)bc * HW_);
    float s = 0.f;
#pragma unroll
    for (int i = 0; i < 16; i++) {
        float4 v = xp[threadIdx.x + 256 * i];
        s += (v.x + v.y) + (v.z + v.w);
    }
#pragma unroll
    for (int o = 16; o; o >>= 1) s += __shfl_xor_sync(0xffffffffu, s, o);
    if ((threadIdx.x & 31) == 0) red[threadIdx.x >> 5] = s;
    __syncthreads();
    if (threadIdx.x < 8) {
        s = red[threadIdx.x];
#pragma unroll
        for (int o = 4; o; o >>= 1) s += __shfl_xor_sync(0x000000ffu, s, o);
        if (threadIdx.x == 0) g_y[bc] = s * (1.0f / (float)HW_);
    }
}

// ---------------- K2: ECA gate + attention MLP + softmax + kernel aggregation -
__global__ void attn_kernel(const float* __restrict__ w1, const float* __restrict__ b1,
                            const float* __restrict__ w2, const float* __restrict__ b2,
                            const float* __restrict__ kw, const float* __restrict__ eca) {
    const int b = blockIdx.x;
    const int t = threadIdx.x;              // 256 threads
    __shared__ float ysm[C_ + 2];
    __shared__ float psm[C_];
    __shared__ float hsm[C_];
    __shared__ float lsm[K_];
    __shared__ float alph[K_];

    ysm[t + 1] = g_y[b * C_ + t];
    if (t == 0) { ysm[0] = 0.f; ysm[C_ + 1] = 0.f; }
    __syncthreads();

    const float e0 = eca[0], e1 = eca[1], e2 = eca[2];
    float gate = sigmoidf_(e0 * ysm[t] + e1 * ysm[t + 1] + e2 * ysm[t + 2]);
    g_gate[b * C_ + t] = gate;
    psm[t] = gate * ysm[t + 1];
    __syncthreads();

    float acc = b1[t];
    for (int c = 0; c < C_; c++) acc += psm[c] * w1[c * C_ + t];
    hsm[t] = gelu_exact(acc);
    __syncthreads();

    if (t < K_) {
        float l = b2[t];
        for (int c = 0; c < C_; c++) l += hsm[c] * w2[c * K_ + t];
        lsm[t] = l;
    }
    __syncthreads();

    if (t == 0) {
        float m = lsm[0];
#pragma unroll
        for (int k = 1; k < K_; k++) m = fmaxf(m, lsm[k]);
        float s = 0.f;
#pragma unroll
        for (int k = 0; k < K_; k++) { float e = __expf(lsm[k] - m); alph[k] = e; s += e; }
        float inv = 1.0f / s;
#pragma unroll
        for (int k = 0; k < K_; k++) alph[k] *= inv;
    }
    __syncthreads();

    for (int idx = t; idx < C_ * 9; idx += 256) {
        float v = 0.f;
#pragma unroll
        for (int k = 0; k < K_; k++) v += alph[k] * kw[k * (C_ * 9) + idx];
        g_aggw[b * (C_ * 9) + idx] = v;
    }
}

// ---------------- K3: fused depthwise conv + LayerNorm(C) + GELU + residual ---
// one block = one 16x8 pixel tile, all 256 channels. 16 warps, each owns 16
// channels with a 4-deep register prefetch pipeline (MLP >> DRAM latency-BW product).
#define SMEM_FLOATS (C_*NPIX + C_*9 + 3*C_ + NWARP*2*HALO_PAD + 2*NWARP*NPIX + 2*NPIX)
#define SMEM_BYTES  (SMEM_FLOATS * 4)

__global__ void __launch_bounds__(512, 1)
fused_kernel(const float* __restrict__ x, const float* __restrict__ gamma,
             const float* __restrict__ beta, float* __restrict__ out) {
    extern __shared__ float smem[];
    float* s_conv  = smem;                          // [256][128]
    float* s_w     = s_conv + C_ * NPIX;            // [256*9]
    float* s_gate  = s_w + C_ * 9;                  // [256]
    float* s_gamma = s_gate + C_;                   // [256]
    float* s_beta  = s_gamma + C_;                  // [256]
    float* s_halo  = s_beta + C_;                   // [16 warps][2 bufs][192]
    float* s_part  = s_halo + NWARP * 2 * HALO_PAD; // [2][16][128]
    float* s_mu    = s_part + 2 * NWARP * NPIX;     // [128]
    float* s_rstd  = s_mu + NPIX;                   // [128]

    const int tid  = threadIdx.x;
    const int warp = tid >> 5;
    const int lane = tid & 31;
    const int b    = blockIdx.z;
    const int h0   = blockIdx.y * TH;
    const int w0   = blockIdx.x * TW;

    for (int i = tid; i < C_ * 9; i += 512) s_w[i] = g_aggw[b * (C_ * 9) + i];
    if (tid < C_) {
        s_gate[tid]  = g_gate[b * C_ + tid];
        s_gamma[tid] = gamma[tid];
        s_beta[tid]  = beta[tid];
    }

    // per-lane halo addressing (fixed across channels)
    int  eoff[6];
    bool eval_[6];
#pragma unroll
    for (int i = 0; i < 6; i++) {
        int e  = lane + 32 * i;
        int r  = e / HALO_W;
        int cc = e - r * HALO_W;
        int gh = h0 - 1 + r;
        int gw = w0 - 1 + cc;
        bool v = (e < HALO_N) && (gh >= 0) && (gh < H_) && (gw >= 0) && (gw < W_);
        eval_[i] = v;
        eoff[i]  = v ? (gh * W_ + gw) : 0;
    }
    __syncthreads();

    const int c_begin = warp * NCH;
    const float* xbase = x + ((size_t)b * C_ + c_begin) * HW_;
    float psum[4] = {0.f, 0.f, 0.f, 0.f};
    float psq[4]  = {0.f, 0.f, 0.f, 0.f};
    float* halo0 = s_halo + warp * 2 * HALO_PAD;
    float* halo1 = halo0 + HALO_PAD;

    // ---- software pipeline: PFD channels in flight ----
    float pre[PFD][6];
#pragma unroll
    for (int d = 0; d < PFD; d++) {
        const float* xc = xbase + (size_t)d * HW_;
#pragma unroll
        for (int i = 0; i < 6; i++) pre[d][i] = eval_[i] ? __ldg(xc + eoff[i]) : 0.f;
    }
    // stage channel 0
#pragma unroll
    for (int i = 0; i < 6; i++) halo0[lane + 32 * i] = pre[0][i];
    __syncwarp();

    float* cur = halo0;
    float* nxt = halo1;
#pragma unroll
    for (int ci = 0; ci < NCH; ci++) {
        // issue loads for channel ci+PFD into the slot just freed
        if (ci + PFD < NCH) {
            const float* xc = xbase + (size_t)(ci + PFD) * HW_;
#pragma unroll
            for (int i = 0; i < 6; i++)
                pre[ci % PFD][i] = eval_[i] ? __ldg(xc + eoff[i]) : 0.f;
        }
        const int c = c_begin + ci;
        const float g = s_gate[c];
        const float* wc = s_w + c * 9;
        const float w00 = wc[0]*g, w01 = wc[1]*g, w02 = wc[2]*g;
        const float w10 = wc[3]*g, w11 = wc[4]*g, w12 = wc[5]*g;
        const float w20 = wc[6]*g, w21 = wc[7]*g, w22 = wc[8]*g;
        float* cb = s_conv + c * NPIX;
#pragma unroll
        for (int q = 0; q < 4; q++) {
            const int p  = lane + 32 * q;
            const int ph = p >> 4;
            const int pw = p & 15;
            const float* hr = cur + ph * HALO_W + pw;
            float a;
            a  = w00 * hr[0]              + w01 * hr[1]               + w02 * hr[2];
            a += w10 * hr[HALO_W]         + w11 * hr[HALO_W + 1]      + w12 * hr[HALO_W + 2];
            a += w20 * hr[2 * HALO_W]     + w21 * hr[2 * HALO_W + 1]  + w22 * hr[2 * HALO_W + 2];
            cb[p]    = a;
            psum[q] += a;
            psq[q]  += a * a;
        }
        __syncwarp();
        if (ci + 1 < NCH) {
#pragma unroll
            for (int i = 0; i < 6; i++) nxt[lane + 32 * i] = pre[(ci + 1) % PFD][i];
            __syncwarp();
            float* tswap = cur; cur = nxt; nxt = tswap;
        }
    }

    // cross-warp LayerNorm stats over C
#pragma unroll
    for (int q = 0; q < 4; q++) {
        const int p = lane + 32 * q;
        s_part[warp * NPIX + p]                 = psum[q];
        s_part[NWARP * NPIX + warp * NPIX + p]  = psq[q];
    }
    __syncthreads();
    if (tid < NPIX) {
        float s = 0.f, s2 = 0.f;
#pragma unroll
        for (int w = 0; w < NWARP; w++) {
            s  += s_part[w * NPIX + tid];
            s2 += s_part[NWARP * NPIX + w * NPIX + tid];
        }
        const float mu  = s * (1.0f / (float)C_);
        const float var = s2 * (1.0f / (float)C_) - mu * mu;
        s_mu[tid]   = mu;
        s_rstd[tid] = rsqrtf(var + 1e-6f);
    }
    __syncthreads();

    // finalize: LN -> GELU -> + residual x, streamed out
#pragma unroll 2
    for (int ci = 0; ci < NCH; ci++) {
        const int c = c_begin + ci;
        const float gm = s_gamma[c];
        const float bt = s_beta[c];
        const float* cb = s_conv + c * NPIX;
        const float* xc = x + ((size_t)b * C_ + c) * HW_;
        float* oc = out + ((size_t)b * C_ + c) * HW_;
#pragma unroll
        for (int q = 0; q < 4; q++) {
            const int p  = lane + 32 * q;
            const int ph = p >> 4;
            const int pw = p & 15;
            const int go = (h0 + ph) * W_ + (w0 + pw);
            const float v = (cb[p] - s_mu[p]) * s_rstd[p] * gm + bt;
            oc[go] = gelu_exact(v) + __ldg(xc + go);
        }
    }
}

// ---------------- launcher -----------------------------------------------------
extern "C" void kernel_launch(void* const* d_in, const int* in_sizes, int n_in,
                              void* d_out, int out_size) {
    const float* x     = (const float*)d_in[0];
    const float* w1    = (const float*)d_in[1];
    const float* b1    = (const float*)d_in[2];
    const float* w2    = (const float*)d_in[3];
    const float* b2    = (const float*)d_in[4];
    const float* kw    = (const float*)d_in[5];
    const float* eca   = (const float*)d_in[6];
    const float* gamma = (const float*)d_in[7];
    const float* beta  = (const float*)d_in[8];
    float* out = (float*)d_out;

    cudaFuncSetAttribute(fused_kernel, cudaFuncAttributeMaxDynamicSharedMemorySize,
                         SMEM_BYTES);

    gap_kernel<<<B_ * C_, 256>>>(x);
    attn_kernel<<<B_, 256>>>(w1, b1, w2, b2, kw, eca);
    dim3 grid(W_ / TW, H_ / TH, B_);
    fused_kernel<<<grid, 512, SMEM_BYTES>>>(x, gamma, beta, out);
}